// round 10
// baseline (speedup 1.0000x reference)
#include <cuda_runtime.h>
#include <cuda_bf16.h>
#include <cstdint>

// ---------------------------------------------------------------------------
// tcgen05 is arch-SPECIFIC (sm_10Xa). The harness also builds a compute_103
// baseline PTX variant which rejects tcgen05 — body must compile away there.
// ---------------------------------------------------------------------------
#if (defined(__CUDA_ARCH_SPECIFIC__) && (__CUDA_ARCH_SPECIFIC__ >= 1000)) || \
    defined(__CUDA_ARCH_FEAT_SM103_ALL) || defined(__CUDA_ARCH_FEAT_SM100_ALL) || \
    defined(__CUDA_ARCH_FEAT_SM101_ALL)
#define HAS_TCGEN05 1
#endif

// ---------------------------------------------------------------------------
#define PAD_ELEMS (32*58*58*128)

// Device scratch (allocation-free rule: __device__ globals)
__device__ __nv_bfloat16 g_qh[PAD_ELEMS];      // padded NHWC uint8-valued acts (high)
__device__ __nv_bfloat16 g_ql[PAD_ELEMS];      // padded NHWC uint4-valued acts (low)
__device__ __nv_bfloat16 g_wqh[9 * 128 * 128]; // [tap][oc][ic]  (K-major B)
__device__ __nv_bfloat16 g_wql[9 * 128 * 128];
__device__ float g_sh[128];                    // s_w_high[oc] * act_scale_high
__device__ float g_sl[128];
__device__ unsigned char g_mask[32 * 128 * 49];

// ---------------------------------------------------------------------------
// PTX helpers
// ---------------------------------------------------------------------------
__device__ __forceinline__ uint32_t smem_u32(const void* p) {
    uint32_t a;
    asm("{ .reg .u64 t; cvta.to.shared.u64 t, %1; cvt.u32.u64 %0, t; }" : "=r"(a) : "l"(p));
    return a;
}

#ifdef HAS_TCGEN05
__device__ __forceinline__ uint32_t elect_one_pred() {
    uint32_t pred;
    asm volatile("{\n\t.reg .pred p;\n\telect.sync _|p, 0xFFFFFFFF;\n\tselp.b32 %0, 1, 0, p;\n\t}" : "=r"(pred));
    return pred;
}
#define MBARRIER_INIT(addr, cnt) \
    asm volatile("mbarrier.init.shared.b64 [%0], %1;" :: "r"(addr), "r"(cnt) : "memory")
#define MBARRIER_WAIT_PARITY(addr, par) do { \
    uint32_t _m = (addr), _p = (par), _d; \
    asm volatile("{\n\t.reg .pred p;\n\tmbarrier.try_wait.parity.acquire.cta.shared::cta.b64 p, [%1], %2;\n\tselp.b32 %0, 1, 0, p;\n\t}" \
        : "=r"(_d) : "r"(_m), "r"(_p) : "memory"); \
    if (!_d) { \
        asm volatile("{\n\t.reg .pred P1;\n\tWL%=:\n\tmbarrier.try_wait.parity.acquire.cta.shared::cta.b64 P1, [%0], %1, 0x989680;\n\t@P1 bra.uni WD%=;\n\tbra.uni WL%=;\n\tWD%=:\n\t}" \
            :: "r"(_m), "r"(_p) : "memory"); \
    } \
} while (0)
#define TCGEN05_ALLOC(saddr, ncols) \
    asm volatile("tcgen05.alloc.cta_group::1.sync.aligned.shared::cta.b32 [%0], %1;" :: "r"(saddr), "r"(ncols) : "memory")
#define TCGEN05_DEALLOC(tm, ncols) \
    asm volatile("tcgen05.dealloc.cta_group::1.sync.aligned.b32 %0, %1;" :: "r"(tm), "r"(ncols))
#define TCGEN05_RELINQ() \
    asm volatile("tcgen05.relinquish_alloc_permit.cta_group::1.sync.aligned;")
#define TCGEN05_COMMIT(mb) \
    asm volatile("tcgen05.commit.cta_group::1.mbarrier::arrive::one.shared::cluster.b64 [%0];" :: "r"(mb) : "memory")
#define TCGEN05_FENCE_AFTER()  asm volatile("tcgen05.fence::after_thread_sync;" ::: "memory")
#define TCGEN05_FENCE_BEFORE() asm volatile("tcgen05.fence::before_thread_sync;" ::: "memory")
#define TCGEN05_WAIT_LD()      asm volatile("tcgen05.wait::ld.sync.aligned;" ::: "memory")
#define FENCE_PROXY_ASYNC()    asm volatile("fence.proxy.async.shared::cta;" ::: "memory")

#define TCGEN05_LD_32X32B_X32(r, a) \
    asm volatile( \
        "tcgen05.ld.sync.aligned.32x32b.x32.b32 " \
        "{%0, %1, %2, %3, %4, %5, %6, %7, %8, %9, %10, %11, %12, %13, %14, %15, " \
        " %16, %17, %18, %19, %20, %21, %22, %23, %24, %25, %26, %27, %28, %29, %30, %31}, [%32];" \
        : "=r"((r)[0]),  "=r"((r)[1]),  "=r"((r)[2]),  "=r"((r)[3]), \
          "=r"((r)[4]),  "=r"((r)[5]),  "=r"((r)[6]),  "=r"((r)[7]), \
          "=r"((r)[8]),  "=r"((r)[9]),  "=r"((r)[10]), "=r"((r)[11]), \
          "=r"((r)[12]), "=r"((r)[13]), "=r"((r)[14]), "=r"((r)[15]), \
          "=r"((r)[16]), "=r"((r)[17]), "=r"((r)[18]), "=r"((r)[19]), \
          "=r"((r)[20]), "=r"((r)[21]), "=r"((r)[22]), "=r"((r)[23]), \
          "=r"((r)[24]), "=r"((r)[25]), "=r"((r)[26]), "=r"((r)[27]), \
          "=r"((r)[28]), "=r"((r)[29]), "=r"((r)[30]), "=r"((r)[31]) \
        : "r"(a))

// bf16 SS MMA, cta_group::1, fp32 accum
__device__ __forceinline__ void mma_f16_ss(uint32_t d, uint64_t ad, uint64_t bd,
                                           uint32_t idesc, uint32_t en) {
    asm volatile(
        "{\n\t.reg .pred p;\n\tsetp.ne.u32 p, %4, 0;\n\t"
        "tcgen05.mma.cta_group::1.kind::f16 [%0], %1, %2, %3, {%5, %5, %5, %5}, p;\n\t}"
        :: "r"(d), "l"(ad), "l"(bd), "r"(idesc), "r"(en), "r"(0u)
        : "memory");
}
#endif // HAS_TCGEN05

// idesc: dtype=F32, atype=btype=BF16, N=128, M=128, K-major both
#define MMA_IDESC 0x8200490u
// SW128 desc: layout=2, version=1, SBO=64 (1024B per 8-row group), LBO=1
#define DESC_BASE_SW128 ((2ull << 61) | (1ull << 46) | (64ull << 32) | (1ull << 16))

// ---------------------------------------------------------------------------
// 1) Pool mask
// ---------------------------------------------------------------------------
__global__ void mask_kernel(const float* __restrict__ x) {
    int cell = blockIdx.x * 8 + (threadIdx.x >> 5);
    int lane = threadIdx.x & 31;
    int b   = cell / (128 * 49);
    int rem = cell - b * (128 * 49);
    int c   = rem / 49;
    int pc  = rem - c * 49;
    int bh  = pc / 7;
    int bw  = pc - bh * 7;
    const float* base = x + (((b * 128 + c) * 56 + bh * 8) * 56 + bw * 8);
    int r = lane >> 3, col = lane & 7;
    float s = base[r * 56 + col] + base[(r + 4) * 56 + col];
#pragma unroll
    for (int o = 16; o > 0; o >>= 1) s += __shfl_xor_sync(0xffffffffu, s, o);
    if (lane == 0) g_mask[cell] = (s * (1.0f / 64.0f)) >= 0.05f ? 1 : 0;
}

// ---------------------------------------------------------------------------
// 2) Zero padded borders
// ---------------------------------------------------------------------------
__global__ void border_kernel() {
    int idx = blockIdx.x * 256 + threadIdx.x;   // < 933888
    int c = idx & 127;
    int t = idx >> 7;
    int b = t / 228;
    int e = t - b * 228;
    int h, w;
    if (e < 58)       { h = 0;  w = e; }
    else if (e < 116) { h = 57; w = e - 58; }
    else { int r = e - 116; h = 1 + (r >> 1); w = (r & 1) ? 57 : 0; }
    long off = (((long)(b * 58 + h)) * 58 + w) * 128 + c;
    __nv_bfloat16 z = __float2bfloat16(0.0f);
    g_qh[off] = z;
    g_ql[off] = z;
}

// ---------------------------------------------------------------------------
// 3) Quantize acts, NCHW -> padded NHWC bf16
// ---------------------------------------------------------------------------
__global__ void quant_kernel(const float* __restrict__ x,
                             const float* __restrict__ p_sh,
                             const float* __restrict__ p_sl) {
    __shared__ float xs[128 * 57];
    __shared__ unsigned char ms[128 * 7];
    int blk = blockIdx.x;
    int b = blk / 56, h = blk - b * 56;
    int tid = threadIdx.x;
    for (int i = tid; i < 128 * 56; i += 256) {
        int c = i / 56, w = i - c * 56;
        xs[c * 57 + w] = x[(((b * 128 + c) * 56 + h)) * 56 + w];
    }
    for (int i = tid; i < 128 * 7; i += 256) {
        int c = i / 7, bw = i - c * 7;
        ms[i] = g_mask[(b * 128 + c) * 49 + (h >> 3) * 7 + bw];
    }
    __syncthreads();
    float sh = *p_sh, sl = *p_sl;
    long pixrow = (((long)(b * 58) + h + 1) * 58 + 1) * 128;
    unsigned int* outh = (unsigned int*)g_qh;
    unsigned int* outl = (unsigned int*)g_ql;
    for (int i = tid; i < 64 * 56; i += 256) {
        int w  = i >> 6;
        int c2 = i & 63;
        int c  = c2 * 2;
        int mb = w >> 3;
        bool m0 = ms[c * 7 + mb] != 0;
        bool m1 = ms[(c + 1) * 7 + mb] != 0;
        float v0 = xs[c * 57 + w], v1 = xs[(c + 1) * 57 + w];
        float q0h = m0 ? fminf(fmaxf(rintf(v0 / sh), 0.f), 255.f) : 0.f;
        float q1h = m1 ? fminf(fmaxf(rintf(v1 / sh), 0.f), 255.f) : 0.f;
        float q0l = m0 ? 0.f : fminf(fmaxf(rintf(v0 / sl), 0.f), 15.f);
        float q1l = m1 ? 0.f : fminf(fmaxf(rintf(v1 / sl), 0.f), 15.f);
        unsigned uh = (unsigned)__bfloat16_as_ushort(__float2bfloat16(q0h)) |
                      ((unsigned)__bfloat16_as_ushort(__float2bfloat16(q1h)) << 16);
        unsigned ul = (unsigned)__bfloat16_as_ushort(__float2bfloat16(q0l)) |
                      ((unsigned)__bfloat16_as_ushort(__float2bfloat16(q1l)) << 16);
        long widx = (pixrow + (long)w * 128 + c) >> 1;
        outh[widx] = uh;
        outl[widx] = ul;
    }
}

// ---------------------------------------------------------------------------
// 4) Weight quantization, high+low merged (one launch): blocks 0..127 high,
//    128..255 low. Writes [tap][oc][ic] bf16.
// ---------------------------------------------------------------------------
__global__ void wq_kernel(const float* __restrict__ wh, const float* __restrict__ wl,
                          const float* __restrict__ ash, const float* __restrict__ asl) {
    __shared__ float red[128];
    int high = blockIdx.x < 128;
    int oc = blockIdx.x & 127;
    int ic = threadIdx.x;
    float n = high ? 127.0f : 7.0f;
    const float* w = high ? wh : wl;
    const float* wp = w + ((long)oc * 128 + ic) * 9;
    float m = 0.f;
#pragma unroll
    for (int t = 0; t < 9; t++) m = fmaxf(m, fabsf(wp[t]));
    red[ic] = m;
    __syncthreads();
    for (int s = 64; s > 0; s >>= 1) {
        if (ic < s) red[ic] = fmaxf(red[ic], red[ic + s]);
        __syncthreads();
    }
    float s_w = red[0] / n;
    __nv_bfloat16* dst = high ? g_wqh : g_wql;
#pragma unroll
    for (int t = 0; t < 9; t++) {
        float q = fminf(fmaxf(rintf(wp[t] / s_w), -n), n);
        dst[t * 16384 + oc * 128 + ic] = __float2bfloat16(q);
    }
    if (ic == 0) (high ? g_sh : g_sl)[oc] = s_w * (high ? *ash : *asl);
}

// ---------------------------------------------------------------------------
// 5) tcgen05 implicit-GEMM dual conv, 2 CTAs/SM.
//    CTA: 128 pixels x 128 oc; TMEM 256 cols/CTA (Dh 0..127, Dl 128..255).
//    36 stages: tap x {H,L} x {k-half}. Stage = A 128x64 (16KB) + B 128x64
//    (16KB), SW128 rows of 128B. 3-deep 32KB ring (96KB) -> occupancy 2.
//    Register double-buffer: preload stage s+1 during MMA(s).
// ---------------------------------------------------------------------------
__global__ void __launch_bounds__(256, 2) conv_kernel(float* __restrict__ out) {
#ifdef HAS_TCGEN05
    extern __shared__ __align__(16) char dsm[];
    __shared__ uint32_t s_tmem;
    __shared__ __align__(8) uint64_t s_bar[3];

    int tid = threadIdx.x;
    int wid = tid >> 5;
    int lane = tid & 31;

    uint32_t base = (smem_u32(dsm) + 1023u) & ~1023u;

    if (tid == 0) {
#pragma unroll
        for (int i = 0; i < 3; i++) MBARRIER_INIT(smem_u32(&s_bar[i]), 1);
    }
    if (wid == 0) TCGEN05_ALLOC(smem_u32(&s_tmem), 256);
    __syncthreads();
    uint32_t tmem = s_tmem;

    // Copy geometry: thread owns rows r0+32j (j=0..3), one 16B chunk per row.
    int col16 = tid & 7;          // which 16B chunk within the 128B row
    int r0 = tid >> 3;
    long rbaseA[4];               // elem offset: pixel row base + chunk
    uint32_t dstoff[4];           // swizzled smem byte offset
    int browB[4];                 // elem offset within weight tap tile
#pragma unroll
    for (int j = 0; j < 4; j++) {
        int row = r0 + 32 * j;
        int g = blockIdx.x * 128 + row;
        int b = g / 3136;
        int r = g - b * 3136;
        int h = r / 56;
        int w = r - h * 56;
        rbaseA[j] = (((long)(b * 58 + h)) * 58 + w) * 128 + col16 * 8;
        uint32_t byte = (uint32_t)row * 128u + (uint32_t)col16 * 16u;
        dstoff[j] = byte ^ ((byte >> 3) & 0x70u);
        browB[j] = row * 128 + col16 * 8;
    }

    uint4 ra[4], rb[4];
    // prologue: stage 0 = tap 0, high, k-half 0
#pragma unroll
    for (int j = 0; j < 4; j++) {
        ra[j] = *(const uint4*)(g_qh + rbaseA[j]);
        rb[j] = *(const uint4*)(g_wqh + browB[j]);
    }

#pragma unroll 1
    for (int s = 0; s < 36; s++) {
        int tap = s >> 2;
        int sub = s & 3;
        int isH = sub < 2;
        int khalf = sub & 1;
        int buf = s % 3;
        uint32_t bufA = base + (uint32_t)buf * 32768u;
        uint32_t bufB = bufA + 16384u;

        if (s >= 3) {
            MBARRIER_WAIT_PARITY(smem_u32(&s_bar[buf]), ((s / 3) - 1) & 1);
        }

#pragma unroll
        for (int j = 0; j < 4; j++) {
            asm volatile("st.shared.v4.b32 [%0], {%1,%2,%3,%4};"
                :: "r"(bufA + dstoff[j]), "r"(ra[j].x), "r"(ra[j].y), "r"(ra[j].z), "r"(ra[j].w));
            asm volatile("st.shared.v4.b32 [%0], {%1,%2,%3,%4};"
                :: "r"(bufB + dstoff[j]), "r"(rb[j].x), "r"(rb[j].y), "r"(rb[j].z), "r"(rb[j].w));
        }
        FENCE_PROXY_ASYNC();
        __syncthreads();

        if (wid == 0 && elect_one_pred()) {
            TCGEN05_FENCE_AFTER();
            uint64_t ad = DESC_BASE_SW128 | ((uint64_t)(bufA >> 4) & 0x3FFF);
            uint64_t bd = DESC_BASE_SW128 | ((uint64_t)(bufB >> 4) & 0x3FFF);
            uint32_t dcol = tmem + (isH ? 0u : 128u);
#pragma unroll
            for (int k = 0; k < 4; k++) {
                mma_f16_ss(dcol, ad + 2 * k, bd + 2 * k, MMA_IDESC,
                           (tap > 0) || (khalf > 0) || (k > 0));
            }
            TCGEN05_COMMIT(smem_u32(&s_bar[buf]));
        }

        // Preload next stage into registers (overlaps async MMA).
        if (s < 35) {
            int s2 = s + 1;
            int tap2 = s2 >> 2;
            int sub2 = s2 & 3;
            const __nv_bfloat16* Asrc = (sub2 < 2) ? g_qh : g_ql;
            const __nv_bfloat16* Bsrc = ((sub2 < 2) ? g_wqh : g_wql) + tap2 * 16384;
            int kh = tap2 / 3, kw = tap2 - kh * 3;
            long aoff = (long)(kh * 58 + kw) * 128 + (sub2 & 1) * 64;
            int boff = (sub2 & 1) * 64;
#pragma unroll
            for (int j = 0; j < 4; j++) {
                ra[j] = *(const uint4*)(Asrc + rbaseA[j] + aoff);
                rb[j] = *(const uint4*)(Bsrc + browB[j] + boff);
            }
        }
    }

    // Drain: 12 commits per buffer -> wait parity 1.
#pragma unroll
    for (int b2 = 0; b2 < 3; b2++) {
        MBARRIER_WAIT_PARITY(smem_u32(&s_bar[b2]), 1);
    }
    TCGEN05_FENCE_AFTER();

    // Epilogue: warps 0-3 cover oc 0..63, warps 4-7 cover oc 64..127.
    int p = (wid & 3) * 32 + lane;
    int g = blockIdx.x * 128 + p;
    int bb = g / 3136;
    int rr = g - bb * 3136;
    float* obase = out + ((long)bb * 128) * 3136 + rr;
    int cb0 = (wid >> 2) * 64;
#pragma unroll
    for (int halfc = 0; halfc < 2; halfc++) {
        int cb = cb0 + 32 * halfc;
        uint32_t rh[32], rl[32];
        TCGEN05_LD_32X32B_X32(rh, tmem + cb);
        TCGEN05_LD_32X32B_X32(rl, tmem + 128 + cb);
        TCGEN05_WAIT_LD();
#pragma unroll
        for (int j = 0; j < 32; j++) {
            int oc = cb + j;
            float y = g_sh[oc] * __uint_as_float(rh[j]) + g_sl[oc] * __uint_as_float(rl[j]);
            obase[(long)oc * 3136] = y;
        }
    }
    TCGEN05_FENCE_BEFORE();
    __syncthreads();
    if (wid == 0) {
        TCGEN05_RELINQ();
        TCGEN05_DEALLOC(tmem, 256);
    }
#endif // HAS_TCGEN05
}

// ---------------------------------------------------------------------------
extern "C" void kernel_launch(void* const* d_in, const int* in_sizes, int n_in,
                              void* d_out, int out_size) {
    const float* x   = (const float*)d_in[0];
    const float* wh  = (const float*)d_in[1];
    const float* wl  = (const float*)d_in[2];
    const float* ash = (const float*)d_in[3];
    const float* asl = (const float*)d_in[4];
    float* out = (float*)d_out;

    cudaFuncSetAttribute(conv_kernel, cudaFuncAttributeMaxDynamicSharedMemorySize, 99328);

    mask_kernel<<<25088, 256>>>(x);              // launch 0
    border_kernel<<<3648, 256>>>();              // launch 1
    quant_kernel<<<1792, 256>>>(x, ash, asl);    // launch 2
    wq_kernel<<<256, 128>>>(wh, wl, ash, asl);   // launch 3 (merged)
    conv_kernel<<<784, 256, 99328>>>(out);       // launch 4 <- ncu target
}

// round 13
// speedup vs baseline: 1.3907x; 1.3907x over previous
#include <cuda_runtime.h>
#include <cuda_bf16.h>
#include <cstdint>

// ---------------------------------------------------------------------------
// tcgen05 is arch-SPECIFIC (sm_10Xa). The harness also builds a compute_103
// baseline PTX variant which rejects tcgen05 — body must compile away there.
// ---------------------------------------------------------------------------
#if (defined(__CUDA_ARCH_SPECIFIC__) && (__CUDA_ARCH_SPECIFIC__ >= 1000)) || \
    defined(__CUDA_ARCH_FEAT_SM103_ALL) || defined(__CUDA_ARCH_FEAT_SM100_ALL) || \
    defined(__CUDA_ARCH_FEAT_SM101_ALL)
#define HAS_TCGEN05 1
#endif

// ---------------------------------------------------------------------------
#define PAD_ELEMS (32*58*58*128)

// Device scratch (allocation-free rule: __device__ globals)
__device__ __nv_bfloat16 g_qh[PAD_ELEMS];      // padded NHWC uint8-valued acts (high)
__device__ __nv_bfloat16 g_ql[PAD_ELEMS];      // padded NHWC uint4-valued acts (low)
__device__ __nv_bfloat16 g_wqh[9 * 128 * 128]; // [tap][oc][ic]  (K-major B)
__device__ __nv_bfloat16 g_wql[9 * 128 * 128];
__device__ float g_sh[128];                    // s_w_high[oc] * act_scale_high
__device__ float g_sl[128];
__device__ unsigned char g_mask[32 * 128 * 49];

// ---------------------------------------------------------------------------
// PTX helpers
// ---------------------------------------------------------------------------
__device__ __forceinline__ uint32_t smem_u32(const void* p) {
    uint32_t a;
    asm("{ .reg .u64 t; cvta.to.shared.u64 t, %1; cvt.u32.u64 %0, t; }" : "=r"(a) : "l"(p));
    return a;
}

#ifdef HAS_TCGEN05
__device__ __forceinline__ uint32_t elect_one_pred() {
    uint32_t pred;
    asm volatile("{\n\t.reg .pred p;\n\telect.sync _|p, 0xFFFFFFFF;\n\tselp.b32 %0, 1, 0, p;\n\t}" : "=r"(pred));
    return pred;
}
#define MBARRIER_INIT(addr, cnt) \
    asm volatile("mbarrier.init.shared.b64 [%0], %1;" :: "r"(addr), "r"(cnt) : "memory")
#define MBARRIER_WAIT_PARITY(addr, par) do { \
    uint32_t _m = (addr), _p = (par), _d; \
    asm volatile("{\n\t.reg .pred p;\n\tmbarrier.try_wait.parity.acquire.cta.shared::cta.b64 p, [%1], %2;\n\tselp.b32 %0, 1, 0, p;\n\t}" \
        : "=r"(_d) : "r"(_m), "r"(_p) : "memory"); \
    if (!_d) { \
        asm volatile("{\n\t.reg .pred P1;\n\tWL%=:\n\tmbarrier.try_wait.parity.acquire.cta.shared::cta.b64 P1, [%0], %1, 0x989680;\n\t@P1 bra.uni WD%=;\n\tbra.uni WL%=;\n\tWD%=:\n\t}" \
            :: "r"(_m), "r"(_p) : "memory"); \
    } \
} while (0)
#define TCGEN05_ALLOC(saddr, ncols) \
    asm volatile("tcgen05.alloc.cta_group::1.sync.aligned.shared::cta.b32 [%0], %1;" :: "r"(saddr), "r"(ncols) : "memory")
#define TCGEN05_DEALLOC(tm, ncols) \
    asm volatile("tcgen05.dealloc.cta_group::1.sync.aligned.b32 %0, %1;" :: "r"(tm), "r"(ncols))
#define TCGEN05_RELINQ() \
    asm volatile("tcgen05.relinquish_alloc_permit.cta_group::1.sync.aligned;")
#define TCGEN05_COMMIT(mb) \
    asm volatile("tcgen05.commit.cta_group::1.mbarrier::arrive::one.shared::cluster.b64 [%0];" :: "r"(mb) : "memory")
#define TCGEN05_FENCE_AFTER()  asm volatile("tcgen05.fence::after_thread_sync;" ::: "memory")
#define TCGEN05_FENCE_BEFORE() asm volatile("tcgen05.fence::before_thread_sync;" ::: "memory")
#define TCGEN05_WAIT_LD()      asm volatile("tcgen05.wait::ld.sync.aligned;" ::: "memory")
#define FENCE_PROXY_ASYNC()    asm volatile("fence.proxy.async.shared::cta;" ::: "memory")

#define TCGEN05_LD_32X32B_X32(r, a) \
    asm volatile( \
        "tcgen05.ld.sync.aligned.32x32b.x32.b32 " \
        "{%0, %1, %2, %3, %4, %5, %6, %7, %8, %9, %10, %11, %12, %13, %14, %15, " \
        " %16, %17, %18, %19, %20, %21, %22, %23, %24, %25, %26, %27, %28, %29, %30, %31}, [%32];" \
        : "=r"((r)[0]),  "=r"((r)[1]),  "=r"((r)[2]),  "=r"((r)[3]), \
          "=r"((r)[4]),  "=r"((r)[5]),  "=r"((r)[6]),  "=r"((r)[7]), \
          "=r"((r)[8]),  "=r"((r)[9]),  "=r"((r)[10]), "=r"((r)[11]), \
          "=r"((r)[12]), "=r"((r)[13]), "=r"((r)[14]), "=r"((r)[15]), \
          "=r"((r)[16]), "=r"((r)[17]), "=r"((r)[18]), "=r"((r)[19]), \
          "=r"((r)[20]), "=r"((r)[21]), "=r"((r)[22]), "=r"((r)[23]), \
          "=r"((r)[24]), "=r"((r)[25]), "=r"((r)[26]), "=r"((r)[27]), \
          "=r"((r)[28]), "=r"((r)[29]), "=r"((r)[30]), "=r"((r)[31]) \
        : "r"(a))

// bf16 SS MMA, cta_group::1, fp32 accum
__device__ __forceinline__ void mma_f16_ss(uint32_t d, uint64_t ad, uint64_t bd,
                                           uint32_t idesc, uint32_t en) {
    asm volatile(
        "{\n\t.reg .pred p;\n\tsetp.ne.u32 p, %4, 0;\n\t"
        "tcgen05.mma.cta_group::1.kind::f16 [%0], %1, %2, %3, {%5, %5, %5, %5}, p;\n\t}"
        :: "r"(d), "l"(ad), "l"(bd), "r"(idesc), "r"(en), "r"(0u)
        : "memory");
}
#endif // HAS_TCGEN05

// idesc: dtype=F32, atype=btype=BF16, N=128, M=128, K-major both
#define MMA_IDESC 0x8200490u
// SW128 desc: layout=2, version=1, SBO=64 (1024B per 8-row group), LBO=1
#define DESC_BASE_SW128 ((2ull << 61) | (1ull << 46) | (64ull << 32) | (1ull << 16))

// ---------------------------------------------------------------------------
// 1) Pool mask
// ---------------------------------------------------------------------------
__global__ void mask_kernel(const float* __restrict__ x) {
    int cell = blockIdx.x * 8 + (threadIdx.x >> 5);
    int lane = threadIdx.x & 31;
    int b   = cell / (128 * 49);
    int rem = cell - b * (128 * 49);
    int c   = rem / 49;
    int pc  = rem - c * 49;
    int bh  = pc / 7;
    int bw  = pc - bh * 7;
    const float* base = x + (((b * 128 + c) * 56 + bh * 8) * 56 + bw * 8);
    int r = lane >> 3, col = lane & 7;
    float s = base[r * 56 + col] + base[(r + 4) * 56 + col];
#pragma unroll
    for (int o = 16; o > 0; o >>= 1) s += __shfl_xor_sync(0xffffffffu, s, o);
    if (lane == 0) g_mask[cell] = (s * (1.0f / 64.0f)) >= 0.05f ? 1 : 0;
}

// ---------------------------------------------------------------------------
// 2) Zero padded borders
// ---------------------------------------------------------------------------
__global__ void border_kernel() {
    int idx = blockIdx.x * 256 + threadIdx.x;   // < 933888
    int c = idx & 127;
    int t = idx >> 7;
    int b = t / 228;
    int e = t - b * 228;
    int h, w;
    if (e < 58)       { h = 0;  w = e; }
    else if (e < 116) { h = 57; w = e - 58; }
    else { int r = e - 116; h = 1 + (r >> 1); w = (r & 1) ? 57 : 0; }
    long off = (((long)(b * 58 + h)) * 58 + w) * 128 + c;
    __nv_bfloat16 z = __float2bfloat16(0.0f);
    g_qh[off] = z;
    g_ql[off] = z;
}

// ---------------------------------------------------------------------------
// 3) Quantize acts, NCHW -> padded NHWC bf16
// ---------------------------------------------------------------------------
__global__ void quant_kernel(const float* __restrict__ x,
                             const float* __restrict__ p_sh,
                             const float* __restrict__ p_sl) {
    __shared__ float xs[128 * 57];
    __shared__ unsigned char ms[128 * 7];
    int blk = blockIdx.x;
    int b = blk / 56, h = blk - b * 56;
    int tid = threadIdx.x;
    for (int i = tid; i < 128 * 56; i += 256) {
        int c = i / 56, w = i - c * 56;
        xs[c * 57 + w] = x[(((b * 128 + c) * 56 + h)) * 56 + w];
    }
    for (int i = tid; i < 128 * 7; i += 256) {
        int c = i / 7, bw = i - c * 7;
        ms[i] = g_mask[(b * 128 + c) * 49 + (h >> 3) * 7 + bw];
    }
    __syncthreads();
    float sh = *p_sh, sl = *p_sl;
    long pixrow = (((long)(b * 58) + h + 1) * 58 + 1) * 128;
    unsigned int* outh = (unsigned int*)g_qh;
    unsigned int* outl = (unsigned int*)g_ql;
    for (int i = tid; i < 64 * 56; i += 256) {
        int w  = i >> 6;
        int c2 = i & 63;
        int c  = c2 * 2;
        int mb = w >> 3;
        bool m0 = ms[c * 7 + mb] != 0;
        bool m1 = ms[(c + 1) * 7 + mb] != 0;
        float v0 = xs[c * 57 + w], v1 = xs[(c + 1) * 57 + w];
        float q0h = m0 ? fminf(fmaxf(rintf(v0 / sh), 0.f), 255.f) : 0.f;
        float q1h = m1 ? fminf(fmaxf(rintf(v1 / sh), 0.f), 255.f) : 0.f;
        float q0l = m0 ? 0.f : fminf(fmaxf(rintf(v0 / sl), 0.f), 15.f);
        float q1l = m1 ? 0.f : fminf(fmaxf(rintf(v1 / sl), 0.f), 15.f);
        unsigned uh = (unsigned)__bfloat16_as_ushort(__float2bfloat16(q0h)) |
                      ((unsigned)__bfloat16_as_ushort(__float2bfloat16(q1h)) << 16);
        unsigned ul = (unsigned)__bfloat16_as_ushort(__float2bfloat16(q0l)) |
                      ((unsigned)__bfloat16_as_ushort(__float2bfloat16(q1l)) << 16);
        long widx = (pixrow + (long)w * 128 + c) >> 1;
        outh[widx] = uh;
        outl[widx] = ul;
    }
}

// ---------------------------------------------------------------------------
// 4) Weight quantization, high+low merged: blocks 0..127 high, 128..255 low.
// ---------------------------------------------------------------------------
__global__ void wq_kernel(const float* __restrict__ wh, const float* __restrict__ wl,
                          const float* __restrict__ ash, const float* __restrict__ asl) {
    __shared__ float red[128];
    int high = blockIdx.x < 128;
    int oc = blockIdx.x & 127;
    int ic = threadIdx.x;
    float n = high ? 127.0f : 7.0f;
    const float* w = high ? wh : wl;
    const float* wp = w + ((long)oc * 128 + ic) * 9;
    float m = 0.f;
#pragma unroll
    for (int t = 0; t < 9; t++) m = fmaxf(m, fabsf(wp[t]));
    red[ic] = m;
    __syncthreads();
    for (int s = 64; s > 0; s >>= 1) {
        if (ic < s) red[ic] = fmaxf(red[ic], red[ic + s]);
        __syncthreads();
    }
    float s_w = red[0] / n;
    __nv_bfloat16* dst = high ? g_wqh : g_wql;
#pragma unroll
    for (int t = 0; t < 9; t++) {
        float q = fminf(fmaxf(rintf(wp[t] / s_w), -n), n);
        dst[t * 16384 + oc * 128 + ic] = __float2bfloat16(q);
    }
    if (ic == 0) (high ? g_sh : g_sl)[oc] = s_w * (high ? *ash : *asl);
}

// ---------------------------------------------------------------------------
// 5) tcgen05 implicit-GEMM dual conv, M=256 per CTA (392 CTAs).
//    TMEM (512 cols): Dh0 @0, Dh1 @128, Dl0 @256, Dl1 @384 (m-half x conv).
//    18 stages (9 taps x {H,L}); stage = A 64KB (two 128x128 SW128 subtiles)
//    + B 32KB; 2-deep ring (192KB, 1 CTA/SM). B traffic halves vs M=128.
//    16 MMA dispatches/stage (2 m-halves x 8 k-chunks), single commit.
// ---------------------------------------------------------------------------
__global__ void __launch_bounds__(256, 1) conv_kernel(float* __restrict__ out) {
#ifdef HAS_TCGEN05
    extern __shared__ __align__(16) char dsm[];
    __shared__ uint32_t s_tmem;
    __shared__ __align__(8) uint64_t s_bar[2];

    int tid = threadIdx.x;
    int wid = tid >> 5;
    int lane = tid & 31;

    uint32_t base = (smem_u32(dsm) + 1023u) & ~1023u;

    if (tid == 0) {
        MBARRIER_INIT(smem_u32(&s_bar[0]), 1);
        MBARRIER_INIT(smem_u32(&s_bar[1]), 1);
    }
    if (wid == 0) TCGEN05_ALLOC(smem_u32(&s_tmem), 512);
    __syncthreads();
    uint32_t tmem = s_tmem;

    // A copy geometry: thread owns rows rowb+16j (j=0..15), chunk col16 (16B).
    // Dest: subtile (row>>7)*32KB + blocked-atom SW128 within 128-row subtile.
    int col16 = tid & 15;
    int rowb = tid >> 4;
    long abase[16];
    uint32_t adst[16];
#pragma unroll
    for (int j = 0; j < 16; j++) {
        int row = rowb + 16 * j;
        int g = blockIdx.x * 256 + row;
        int b = g / 3136;
        int r = g - b * 3136;
        int h = r / 56;
        int w = r - h * 56;
        abase[j] = (((long)(b * 58 + h)) * 58 + w) * 128 + col16 * 8;
        int rr = row & 127;
        uint32_t off = ((uint32_t)(rr >> 3) + ((uint32_t)(col16 >> 3) << 4)) * 1024u
                       + (uint32_t)(rr & 7) * 128u + (uint32_t)(col16 & 7) * 16u;
        adst[j] = (uint32_t)(row >> 7) * 32768u + (off ^ ((off >> 3) & 0x70u));
    }
    // B copy geometry: rows rowb+16j (j=0..7), same chunk scheme.
    uint32_t bdst[8];
    int bsrc[8];
#pragma unroll
    for (int j = 0; j < 8; j++) {
        int row = rowb + 16 * j;
        uint32_t off = ((uint32_t)(row >> 3) + ((uint32_t)(col16 >> 3) << 4)) * 1024u
                       + (uint32_t)(row & 7) * 128u + (uint32_t)(col16 & 7) * 16u;
        bdst[j] = off ^ ((off >> 3) & 0x70u);
        bsrc[j] = row * 128 + col16 * 8;
    }

    const int koff[8] = {0, 2, 4, 6, 1024, 1026, 1028, 1030};

#pragma unroll 1
    for (int s = 0; s < 18; s++) {
        int tap = s >> 1;
        int isH = !(s & 1);
        int buf = s & 1;
        uint32_t bufA = base + (uint32_t)buf * 98304u;
        uint32_t bufB = bufA + 65536u;

        if (s >= 2) {
            MBARRIER_WAIT_PARITY(smem_u32(&s_bar[buf]), ((s >> 1) - 1) & 1);
        }

        const __nv_bfloat16* Asrc = isH ? g_qh : g_ql;
        const __nv_bfloat16* Bsrc = (isH ? g_wqh : g_wql) + tap * 16384;
        int kh = tap / 3, kw = tap - kh * 3;
        long tapoff = (long)(kh * 58 + kw) * 128;

#pragma unroll
        for (int j = 0; j < 16; j++) {
            uint4 v = *(const uint4*)(Asrc + abase[j] + tapoff);
            asm volatile("st.shared.v4.b32 [%0], {%1,%2,%3,%4};"
                :: "r"(bufA + adst[j]), "r"(v.x), "r"(v.y), "r"(v.z), "r"(v.w));
        }
#pragma unroll
        for (int j = 0; j < 8; j++) {
            uint4 v = *(const uint4*)(Bsrc + bsrc[j]);
            asm volatile("st.shared.v4.b32 [%0], {%1,%2,%3,%4};"
                :: "r"(bufB + bdst[j]), "r"(v.x), "r"(v.y), "r"(v.z), "r"(v.w));
        }
        FENCE_PROXY_ASYNC();
        __syncthreads();

        if (wid == 0 && elect_one_pred()) {
            TCGEN05_FENCE_AFTER();
            uint64_t bd = DESC_BASE_SW128 | ((uint64_t)(bufB >> 4) & 0x3FFF);
            uint32_t dbase = tmem + (isH ? 0u : 256u);
#pragma unroll
            for (int m = 0; m < 2; m++) {
                uint64_t ad = DESC_BASE_SW128 | ((uint64_t)((bufA + m * 32768u) >> 4) & 0x3FFF);
                uint32_t dcol = dbase + m * 128u;
#pragma unroll
                for (int k = 0; k < 8; k++) {
                    mma_f16_ss(dcol, ad + koff[k], bd + koff[k], MMA_IDESC,
                               (s >= 2) || (k > 0));
                }
            }
            TCGEN05_COMMIT(smem_u32(&s_bar[buf]));
        }
    }

    // Drain: 9 commits per buffer -> wait parity (9-1)&1 = 0.
    MBARRIER_WAIT_PARITY(smem_u32(&s_bar[0]), 0);
    MBARRIER_WAIT_PARITY(smem_u32(&s_bar[1]), 0);
    TCGEN05_FENCE_AFTER();

    // Epilogue: warps 0-3 -> m-half 0, warps 4-7 -> m-half 1 (same TMEM lanes,
    // different column block). Each warp covers 32 pixels x all 128 oc.
    int mh = wid >> 2;
    int p = mh * 128 + (wid & 3) * 32 + lane;
    int g = blockIdx.x * 256 + p;
    int bb = g / 3136;
    int rr = g - bb * 3136;
    float* obase = out + ((long)bb * 128) * 3136 + rr;
    uint32_t dh = tmem + (uint32_t)mh * 128u;
    uint32_t dl = dh + 256u;
#pragma unroll
    for (int cbi = 0; cbi < 4; cbi++) {
        int cb = cbi * 32;
        uint32_t rh[32], rl[32];
        TCGEN05_LD_32X32B_X32(rh, dh + cb);
        TCGEN05_LD_32X32B_X32(rl, dl + cb);
        TCGEN05_WAIT_LD();
#pragma unroll
        for (int j = 0; j < 32; j++) {
            int oc = cb + j;
            float y = g_sh[oc] * __uint_as_float(rh[j]) + g_sl[oc] * __uint_as_float(rl[j]);
            obase[(long)oc * 3136] = y;
        }
    }
    TCGEN05_FENCE_BEFORE();
    __syncthreads();
    if (wid == 0) {
        TCGEN05_RELINQ();
        TCGEN05_DEALLOC(tmem, 512);
    }
#endif // HAS_TCGEN05
}

// ---------------------------------------------------------------------------
extern "C" void kernel_launch(void* const* d_in, const int* in_sizes, int n_in,
                              void* d_out, int out_size) {
    const float* x   = (const float*)d_in[0];
    const float* wh  = (const float*)d_in[1];
    const float* wl  = (const float*)d_in[2];
    const float* ash = (const float*)d_in[3];
    const float* asl = (const float*)d_in[4];
    float* out = (float*)d_out;

    cudaFuncSetAttribute(conv_kernel, cudaFuncAttributeMaxDynamicSharedMemorySize, 197632);

    mask_kernel<<<25088, 256>>>(x);
    border_kernel<<<3648, 256>>>();
    quant_kernel<<<1792, 256>>>(x, ash, asl);
    wq_kernel<<<256, 128>>>(wh, wl, ash, asl);
    conv_kernel<<<392, 256, 197632>>>(out);
}